// round 16
// baseline (speedup 1.0000x reference)
#include <cuda_runtime.h>
#include <cuda_fp16.h>

// Problem shape (fixed by the dataset)
#define BATCH 8
#define CHAN  3
#define HH    720
#define WW    1280
#define HW    (HH * WW)
#define NROWS (BATCH * HH)
#define EPSV  1e-6f
#define K_LOG2 0.49978218f     // log2(1.414)

// flow_y == 0 -> 1-D row splat: pixel x hits bins x0=floor(x-d) and x0+1.
// (c0,c1) and (c2,wsum) accumulate as two __half2 shared planes per row via
// return-free red.shared.add.noftz.f16x2 (4 REDs/px = exact payload floor;
// ~12cyc/RED is RMW fixed cost, mapping-invariant).
//
// R16: two rows per block, PARALLEL across warp halves (not sequential like
// the failed R11/R13): 640 threads, warps 0-9 -> row A, warps 10-19 -> row B.
// Per-thread shape identical to the R10 champion (4 px, one row, regs ~32),
// so occupancy math: 3 CTAs x 640 = 1920 threads, but barriers per row halve
// and the two halves' RED bursts interleave to hide load latency.
__device__ __forceinline__ int bhash(int bin) {
    return bin ^ ((bin >> 5) & 28);
}

__device__ __forceinline__ void red_sh_h2(unsigned addr, unsigned val) {
    asm volatile("red.shared.add.noftz.f16x2 [%0], %1;"
                 :: "r"(addr), "r"(val) : "memory");
}

__device__ __forceinline__ unsigned pack_h2(float a, float b) {
    __half2 h = __floats2half2_rn(a, b);
    return *(unsigned*)&h;
}

__global__ __launch_bounds__(640) void splat_kernel(
    const float* __restrict__ im,
    const float* __restrict__ disp,
    float* __restrict__ out)
{
    __shared__ __half2 sA[2][WW];   // (c0, c1), hashed slots, one per sub-row
    __shared__ __half2 sB[2][WW];   // (c2, w )

    const int tid  = threadIdx.x;
    const int half = tid >= 320;         // 0: row A, 1: row B
    const int tidr = tid - half * 320;   // 0..319 within the half

    const int row = blockIdx.x * 2 + half;   // HH even -> same batch per block
    const int b   = row / HH;
    const int y   = row - b * HH;

    const unsigned baseA = (unsigned)__cvta_generic_to_shared(sA[half]);
    const unsigned baseB = (unsigned)__cvta_generic_to_shared(sB[half]);

    // ---- zero this half's planes: 2 * 320 uint4 ----
    ((uint4*)sA[half])[tidr] = make_uint4(0u, 0u, 0u, 0u);
    ((uint4*)sB[half])[tidr] = make_uint4(0u, 0u, 0u, 0u);
    __syncthreads();

    const float* d_row  = disp + (size_t)row * WW;
    const float* im_row = im  + (size_t)b * CHAN * HW + (size_t)y * WW;
    float*       o_row  = out + (size_t)b * CHAN * HW + (size_t)y * WW;

    // ---- splat phase: 4 consecutive pixels per thread ----
    const int xb = tidr * 4;
    float4 d4 = ((const float4*)d_row)[tidr];
    float4 c0 = ((const float4*)(im_row))[tidr];
    float4 c1 = ((const float4*)(im_row + HW))[tidr];
    float4 c2 = ((const float4*)(im_row + 2 * HW))[tidr];

    const float dd[4] = {d4.x, d4.y, d4.z, d4.w};
    const float p0[4] = {c0.x, c0.y, c0.z, c0.w};
    const float p1[4] = {c1.x, c1.y, c1.z, c1.w};
    const float p2[4] = {c2.x, c2.y, c2.z, c2.w};

    // precompute payloads/addresses, then fire REDs (no return deps)
    unsigned adrA[8], adrB[8], valA[8], valB[8];
    bool ok[8];
    #pragma unroll
    for (int k = 0; k < 4; k++) {
        float d = dd[k];
        float w;
        asm("ex2.approx.f32 %0, %1;" : "=f"(w) : "f"(d * K_LOG2));
        float tx  = (float)(xb + k) - d;
        int   x0  = __float2int_rd(tx);
        float fc  = tx - (float)x0;   // weight toward x0+1
        float wc  = w * fc;           // combined weight at x0+1
        float wa  = w - wc;           // combined weight at x0

        float v0 = p0[k], v1 = p1[k], v2 = p2[k];

        int h0 = bhash(x0);
        int h1 = bhash(x0 + 1);
        ok[2 * k]     = (unsigned)x0 < WW;        // x0 in [x-21, x]
        ok[2 * k + 1] = (unsigned)(x0 + 1) < WW;
        adrA[2 * k]     = baseA + 4u * h0;
        adrB[2 * k]     = baseB + 4u * h0;
        adrA[2 * k + 1] = baseA + 4u * h1;
        adrB[2 * k + 1] = baseB + 4u * h1;
        valA[2 * k]     = pack_h2(v0 * wa, v1 * wa);
        valB[2 * k]     = pack_h2(v2 * wa, wa);
        valA[2 * k + 1] = pack_h2(v0 * wc, v1 * wc);
        valB[2 * k + 1] = pack_h2(v2 * wc, wc);
    }
    #pragma unroll
    for (int i = 0; i < 8; i++) {
        if (ok[i]) {
            red_sh_h2(adrA[i], valA[i]);
            red_sh_h2(adrB[i], valB[i]);
        }
    }
    __syncthreads();

    // ---- normalize: hash keeps aligned 4-bin groups contiguous/ordered ----
    const int g = (xb ^ ((xb >> 5) & 28)) >> 2;
    uint4 ua = ((const uint4*)sA[half])[g];
    uint4 ub = ((const uint4*)sB[half])[g];
    const unsigned va[4] = {ua.x, ua.y, ua.z, ua.w};
    const unsigned vb[4] = {ub.x, ub.y, ub.z, ub.w};

    float4 r0, r1, r2;
    float* r0p = &r0.x; float* r1p = &r1.x; float* r2p = &r2.x;
    #pragma unroll
    for (int j = 0; j < 4; j++) {
        __half2 a  = *(const __half2*)&va[j];
        __half2 bb = *(const __half2*)&vb[j];
        float n0 = __low2float(a),  n1 = __high2float(a);
        float n2 = __low2float(bb), ws = __high2float(bb);
        float inv;
        asm("rcp.approx.f32 %0, %1;" : "=f"(inv) : "f"(fmaxf(ws, EPSV)));
        r0p[j] = n0 * inv;
        r1p[j] = n1 * inv;
        r2p[j] = n2 * inv;
    }
    ((float4*)o_row)[tidr]            = r0;
    ((float4*)(o_row + HW))[tidr]     = r1;
    ((float4*)(o_row + 2 * HW))[tidr] = r2;
}

extern "C" void kernel_launch(void* const* d_in, const int* in_sizes, int n_in,
                              void* d_out, int out_size) {
    const float* im   = (const float*)d_in[0];   // [8,3,720,1280] fp32
    const float* disp = (const float*)d_in[1];   // [8,1,720,1280] fp32
    float* out = (float*)d_out;                  // [8,3,720,1280] fp32

    splat_kernel<<<NROWS / 2, 640>>>(im, disp, out);
}

// round 17
// speedup vs baseline: 1.0302x; 1.0302x over previous
#include <cuda_runtime.h>
#include <cuda_fp16.h>

// Problem shape (fixed by the dataset)
#define BATCH 8
#define CHAN  3
#define HH    720
#define WW    1280
#define HW    (HH * WW)
#define NROWS (BATCH * HH)
#define NT    640
#define EPSV  1e-6f
#define K_LOG2 0.49978218f     // log2(1.414)

// flow_y == 0 -> 1-D row splat: pixel x hits bins x0=floor(x-d) and x0+1.
// (c0,c1) and (c2,wsum) accumulate as two __half2 shared planes via
// return-free red.shared.add.noftz.f16x2 (4 REDs/px = exact payload floor;
// ~12cyc/RED RMW fixed cost, mapping-invariant across 5 tested layouts).
//
// R17: 640 threads x 2 px/thread, one row per block. Same resident threads
// as the R10 champion (3x640 = 6x320 = 1920/SM) but halved per-thread
// staging (regs down), no tail pixel, and 20 warps/block of independent RED
// streams per barrier cohort. Every prior structural variant inflated regs;
// this is the only shape that shrinks them.
__device__ __forceinline__ int bhash(int bin) {
    return bin ^ ((bin >> 5) & 28);
}

__device__ __forceinline__ void red_sh_h2(unsigned addr, unsigned val) {
    asm volatile("red.shared.add.noftz.f16x2 [%0], %1;"
                 :: "r"(addr), "r"(val) : "memory");
}

__device__ __forceinline__ unsigned pack_h2(float a, float b) {
    __half2 h = __floats2half2_rn(a, b);
    return *(unsigned*)&h;
}

__global__ __launch_bounds__(NT) void splat_kernel(
    const float* __restrict__ im,
    const float* __restrict__ disp,
    float* __restrict__ out)
{
    __shared__ __half2 sA[WW];   // (c0, c1), hashed slots
    __shared__ __half2 sB[WW];   // (c2, w ), hashed slots

    const int row = blockIdx.x;      // b*HH + y
    const int b   = row / HH;
    const int y   = row - b * HH;
    const int tid = threadIdx.x;

    const unsigned baseA = (unsigned)__cvta_generic_to_shared(sA);
    const unsigned baseB = (unsigned)__cvta_generic_to_shared(sB);

    // ---- zero both planes: 640 uint4 total, 1 per thread ----
    if (tid < 320) ((uint4*)sA)[tid]       = make_uint4(0u, 0u, 0u, 0u);
    else           ((uint4*)sB)[tid - 320] = make_uint4(0u, 0u, 0u, 0u);
    __syncthreads();

    const float* d_row  = disp + (size_t)row * WW;
    const float* im_row = im  + (size_t)b * CHAN * HW + (size_t)y * WW;
    float*       o_row  = out + (size_t)b * CHAN * HW + (size_t)y * WW;

    // ---- splat phase: 2 consecutive pixels per thread (float2 loads) ----
    const int xb = tid * 2;
    float2 d2 = ((const float2*)d_row)[tid];
    float2 c0 = ((const float2*)(im_row))[tid];
    float2 c1 = ((const float2*)(im_row + HW))[tid];
    float2 c2 = ((const float2*)(im_row + 2 * HW))[tid];

    const float dd[2] = {d2.x, d2.y};
    const float p0[2] = {c0.x, c0.y};
    const float p1[2] = {c1.x, c1.y};
    const float p2[2] = {c2.x, c2.y};

    // precompute payloads/addresses, then fire REDs (no return deps)
    unsigned adrA[4], adrB[4], valA[4], valB[4];
    bool ok[4];
    #pragma unroll
    for (int k = 0; k < 2; k++) {
        float d = dd[k];
        float w;
        asm("ex2.approx.f32 %0, %1;" : "=f"(w) : "f"(d * K_LOG2));
        float tx  = (float)(xb + k) - d;
        int   x0  = __float2int_rd(tx);
        float fc  = tx - (float)x0;   // weight toward x0+1
        float wc  = w * fc;           // combined weight at x0+1
        float wa  = w - wc;           // combined weight at x0

        float v0 = p0[k], v1 = p1[k], v2 = p2[k];

        int h0 = bhash(x0);
        int h1 = bhash(x0 + 1);
        ok[2 * k]     = (unsigned)x0 < WW;        // x0 in [x-21, x]
        ok[2 * k + 1] = (unsigned)(x0 + 1) < WW;
        adrA[2 * k]     = baseA + 4u * h0;
        adrB[2 * k]     = baseB + 4u * h0;
        adrA[2 * k + 1] = baseA + 4u * h1;
        adrB[2 * k + 1] = baseB + 4u * h1;
        valA[2 * k]     = pack_h2(v0 * wa, v1 * wa);
        valB[2 * k]     = pack_h2(v2 * wa, wa);
        valA[2 * k + 1] = pack_h2(v0 * wc, v1 * wc);
        valB[2 * k + 1] = pack_h2(v2 * wc, wc);
    }
    #pragma unroll
    for (int i = 0; i < 4; i++) {
        if (ok[i]) {
            red_sh_h2(adrA[i], valA[i]);
            red_sh_h2(adrB[i], valB[i]);
        }
    }
    __syncthreads();

    // ---- normalize: bins 2t, 2t+1. Hash flips only bits 2..4, so the
    // aligned pair stays contiguous and ordered: one uint2 per plane. ----
    const int g = (xb ^ ((xb >> 5) & 28)) >> 1;
    uint2 ua = ((const uint2*)sA)[g];
    uint2 ub = ((const uint2*)sB)[g];
    const unsigned va[2] = {ua.x, ua.y};
    const unsigned vb[2] = {ub.x, ub.y};

    float2 r0, r1, r2;
    float* r0p = &r0.x; float* r1p = &r1.x; float* r2p = &r2.x;
    #pragma unroll
    for (int j = 0; j < 2; j++) {
        __half2 a  = *(const __half2*)&va[j];
        __half2 bb = *(const __half2*)&vb[j];
        float n0 = __low2float(a),  n1 = __high2float(a);
        float n2 = __low2float(bb), ws = __high2float(bb);
        float inv;
        asm("rcp.approx.f32 %0, %1;" : "=f"(inv) : "f"(fmaxf(ws, EPSV)));
        r0p[j] = n0 * inv;
        r1p[j] = n1 * inv;
        r2p[j] = n2 * inv;
    }
    ((float2*)o_row)[tid]            = r0;
    ((float2*)(o_row + HW))[tid]     = r1;
    ((float2*)(o_row + 2 * HW))[tid] = r2;
}

extern "C" void kernel_launch(void* const* d_in, const int* in_sizes, int n_in,
                              void* d_out, int out_size) {
    const float* im   = (const float*)d_in[0];   // [8,3,720,1280] fp32
    const float* disp = (const float*)d_in[1];   // [8,1,720,1280] fp32
    float* out = (float*)d_out;                  // [8,3,720,1280] fp32

    splat_kernel<<<NROWS, NT>>>(im, disp, out);
}